// round 7
// baseline (speedup 1.0000x reference)
#include <cuda_runtime.h>
#include <cuda_fp16.h>

#define NN   50000
#define EE   800000
#define INC  128
#define OUTC 32
#define HH   4
#define EDIM 16
#define HO   128          // H*OUT
#define ENF  (EE + NN)    // edges + self loops = 850000 (divisible by 16)
#define NBATCH (ENF / 16) // 53125 warp batches
#define SLOPE 0.2f

// ---------------- scratch (device globals; no allocation allowed) ----------
__device__ float    g_xl[(size_t)NN * HO];       // x @ W_l + b_l   (25.6 MB)
__device__ float    g_xr[(size_t)NN * HO];       // x @ W_r + b_r   (25.6 MB)
__device__ float    g_deg[NN];                   // in-degree
__device__ float    g_asum[(size_t)NN * EDIM];   // scatter-sum of edge attrs
__device__ float    g_denom[(size_t)NN * HH];    // softmax denominators
__device__ float4   g_accum[(size_t)NN * OUTC];  // sum exp(s) * x_l[src]  (25.6 MB)
// E in mma-fragment permuted order: [batch][tile 0..15][sel 0..1][lane 0..31]
__device__ unsigned g_eperm[(size_t)NBATCH * 1024];   // fp16x2 words (217.6 MB)

// ---------------- helpers --------------------------------------------------
__device__ __forceinline__ float lrelu(float v) { return v > 0.f ? v : SLOPE * v; }

__device__ __forceinline__ void red_add_v4(float4* addr, float4 v) {
    asm volatile("red.global.add.v4.f32 [%0], {%1,%2,%3,%4};"
                 :: "l"(addr), "f"(v.x), "f"(v.y), "f"(v.z), "f"(v.w)
                 : "memory");
}

// pack two f32 into f16x2: lo -> bits[15:0], hi -> bits[31:16]
__device__ __forceinline__ unsigned pack_h2(float hi, float lo) {
    unsigned r;
    asm("cvt.rn.f16x2.f32 %0, %1, %2;" : "=r"(r) : "f"(hi), "f"(lo));
    return r;
}

// packed fp32x2 FMA (Blackwell FFMA2 — only reachable via PTX)
__device__ __forceinline__ unsigned long long pk2(float lo, float hi) {
    unsigned long long r;
    asm("mov.b64 %0, {%1, %2};" : "=l"(r) : "f"(lo), "f"(hi));
    return r;
}
__device__ __forceinline__ void fma2(unsigned long long& d, unsigned long long a,
                                     unsigned long long b, unsigned long long c) {
    asm("fma.rn.f32x2 %0, %1, %2, %3;" : "=l"(d) : "l"(a), "l"(b), "l"(c));
}
__device__ __forceinline__ float2 upk2(unsigned long long v) {
    float2 f;
    asm("mov.b64 {%0, %1}, %2;" : "=f"(f.x), "=f"(f.y) : "l"(v));
    return f;
}

// ---------------- kernel 1: zero scratch -----------------------------------
__global__ void zero_kernel() {
    long i = (long)blockIdx.x * blockDim.x + threadIdx.x;
    long stride = (long)gridDim.x * blockDim.x;
    float* acc = (float*)g_accum;
    for (long j = i; j < (long)NN * HO; j += stride) acc[j] = 0.f;
    for (long j = i; j < (long)NN * HH; j += stride) g_denom[j] = 0.f;
    for (long j = i; j < (long)NN; j += stride) g_deg[j] = 0.f;
    for (long j = i; j < (long)NN * EDIM; j += stride) g_asum[j] = 0.f;
}

// ---------------- kernel 2: degree + attr scatter-sum (vectorized) ---------
__global__ void deg_attr_kernel(const int* __restrict__ ei,
                                const float* __restrict__ eattr) {
    int e = blockIdx.x * blockDim.x + threadIdx.x;
    if (e >= EE) return;
    int t = ei[EE + e];
    const float4* a4 = (const float4*)&eattr[(long)e * EDIM];
    float4* dst = &((float4*)g_asum)[(long)t * 4];
#pragma unroll
    for (int q = 0; q < 4; q++) red_add_v4(&dst[q], a4[q]);
    atomicAdd(&g_deg[t], 1.f);
}

// ---------------- kernel 3: x_l / x_r GEMMs with FFMA2 ---------------------
__global__ void gemm_xlr(const float* __restrict__ x,
                         const float* __restrict__ Wl, const float* __restrict__ bl,
                         const float* __restrict__ Wr, const float* __restrict__ br) {
    __shared__ float xs[64][INC];
    int row0 = blockIdx.x * 64;
    int tid = threadIdx.x;

    const float4* x4 = (const float4*)x;
    for (int i = tid; i < 64 * 32; i += 256) {
        int r = i >> 5, c = i & 31;
        float4 v = make_float4(0.f, 0.f, 0.f, 0.f);
        if (row0 + r < NN) v = x4[(long)(row0 + r) * 32 + c];
        ((float4*)xs[r])[c] = v;
    }
    __syncthreads();

    int tx = tid & 31, ty = tid >> 5;
    unsigned long long accL[8][2], accR[8][2];
    unsigned long long z2 = pk2(0.f, 0.f);
#pragma unroll
    for (int r = 0; r < 8; r++) {
        accL[r][0] = z2; accL[r][1] = z2;
        accR[r][0] = z2; accR[r][1] = z2;
    }
    const float4* Wl4 = (const float4*)Wl;
    const float4* Wr4 = (const float4*)Wr;
    for (int k = 0; k < INC; k++) {
        float4 wl = Wl4[k * 32 + tx];
        float4 wr = Wr4[k * 32 + tx];
        unsigned long long wl0 = pk2(wl.x, wl.y), wl1 = pk2(wl.z, wl.w);
        unsigned long long wr0 = pk2(wr.x, wr.y), wr1 = pk2(wr.z, wr.w);
#pragma unroll
        for (int r = 0; r < 8; r++) {
            float xv = xs[ty + r * 8][k];
            unsigned long long xv2 = pk2(xv, xv);
            fma2(accL[r][0], xv2, wl0, accL[r][0]);
            fma2(accL[r][1], xv2, wl1, accL[r][1]);
            fma2(accR[r][0], xv2, wr0, accR[r][0]);
            fma2(accR[r][1], xv2, wr1, accR[r][1]);
        }
    }
    float4 blv = ((const float4*)bl)[tx];
    float4 brv = ((const float4*)br)[tx];
#pragma unroll
    for (int r = 0; r < 8; r++) {
        int row = row0 + ty + r * 8;
        if (row < NN) {
            float2 l0 = upk2(accL[r][0]), l1 = upk2(accL[r][1]);
            float2 r0 = upk2(accR[r][0]), r1 = upk2(accR[r][1]);
            ((float4*)g_xl)[(long)row * 32 + tx] =
                make_float4(l0.x + blv.x, l0.y + blv.y, l1.x + blv.z, l1.y + blv.w);
            ((float4*)g_xr)[(long)row * 32 + tx] =
                make_float4(r0.x + brv.x, r0.y + brv.y, r1.x + brv.z, r1.y + brv.w);
        }
    }
}

// ---------------- kernel 4: edge projection via tensor cores ---------------
// Each warp computes a 16-row x 128-col tile of E = attr_full @ W_e using
// 16x mma.sync.m16n8k16 (fp16 in, fp32 acc). W_e B-fragments cached in regs.
// E is stored fp16 in FRAGMENT-PERMUTED order (no epilogue shuffle needed):
//   word index = batch*1024 + tile*64 + sel*32 + srclane
// where sel 0/1 = rows grp / grp+8.  Self-loop rows use scatter-mean attrs.
__global__ void __launch_bounds__(256)
egemm_mma_kernel(const float* __restrict__ eattr,
                 const float* __restrict__ We) {
    int lane = threadIdx.x & 31;
    long warpid = (long)blockIdx.x * 8 + (threadIdx.x >> 5);
    if (warpid >= NBATCH) return;
    int grp = lane >> 2, ctg = lane & 3;

    // B fragments for all 16 n-tiles: b0 = k rows 2ctg,2ctg+1; b1 = +8
    unsigned b0[16], b1[16];
#pragma unroll
    for (int t = 0; t < 16; t++) {
        int col = t * 8 + grp;
        float x0 = __ldg(&We[(2 * ctg) * HO + col]);
        float x1 = __ldg(&We[(2 * ctg + 1) * HO + col]);
        float x2 = __ldg(&We[(2 * ctg + 8) * HO + col]);
        float x3 = __ldg(&We[(2 * ctg + 9) * HO + col]);
        b0[t] = pack_h2(x1, x0);
        b1[t] = pack_h2(x3, x2);
    }

    // A fragments: rows base+grp (a0,a2) and base+grp+8 (a1,a3)
    long base = warpid * 16;
    unsigned a0, a1, a2, a3;
    {
        long row = base + grp;
        const float* p; float inv = 1.f;
        if (row < EE) { p = &eattr[row * EDIM]; }
        else { int n = (int)(row - EE); p = &g_asum[(size_t)n * EDIM];
               inv = 1.f / fmaxf(g_deg[n], 1.f); }
        float2 lo = *(const float2*)(p + 2 * ctg);
        float2 hi = *(const float2*)(p + 2 * ctg + 8);
        a0 = pack_h2(lo.y * inv, lo.x * inv);
        a2 = pack_h2(hi.y * inv, hi.x * inv);
    }
    {
        long row = base + grp + 8;
        const float* p; float inv = 1.f;
        if (row < EE) { p = &eattr[row * EDIM]; }
        else { int n = (int)(row - EE); p = &g_asum[(size_t)n * EDIM];
               inv = 1.f / fmaxf(g_deg[n], 1.f); }
        float2 lo = *(const float2*)(p + 2 * ctg);
        float2 hi = *(const float2*)(p + 2 * ctg + 8);
        a1 = pack_h2(lo.y * inv, lo.x * inv);
        a3 = pack_h2(hi.y * inv, hi.x * inv);
    }

    unsigned* outp = g_eperm + (size_t)warpid * 1024;
    float z = 0.f;
#pragma unroll
    for (int t = 0; t < 16; t++) {
        float d0, d1, d2, d3;
        asm volatile(
            "mma.sync.aligned.m16n8k16.row.col.f32.f16.f16.f32 "
            "{%0,%1,%2,%3}, {%4,%5,%6,%7}, {%8,%9}, {%10,%10,%10,%10};"
            : "=f"(d0), "=f"(d1), "=f"(d2), "=f"(d3)
            : "r"(a0), "r"(a1), "r"(a2), "r"(a3),
              "r"(b0[t]), "r"(b1[t]), "f"(z));
        outp[t * 64 + lane]      = pack_h2(d1, d0);   // rows grp   (sel 0)
        outp[t * 64 + 32 + lane] = pack_h2(d3, d2);   // rows grp+8 (sel 1)
    }
}

// ---------------- kernel 5: LIGHT edge pass --------------------------------
// One warp per edge; lane owns channel quad 4*lane..4*lane+3. Reads E from
// the fragment-permuted buffer with a single LDG.64 per lane.
__global__ void __launch_bounds__(256)
edge_light_kernel(const int* __restrict__ ei,
                  const float* __restrict__ att) {
    int lane = threadIdx.x & 31;
    long ew = (long)blockIdx.x * 8 + (threadIdx.x >> 5);
    if (ew >= ENF) return;

    int s, t;
    if (ew < EE) { s = __ldg(&ei[ew]); t = __ldg(&ei[EE + ew]); }
    else         { s = t = (int)(ew - EE); }

    float4 xl = __ldg(&((const float4*)g_xl)[(long)s * 32 + lane]);
    float4 xr = __ldg(&((const float4*)g_xr)[(long)t * 32 + lane]);

    // E from fragment-permuted layout
    long batch = ew >> 4;
    int g16 = (int)(ew & 15);
    int sel = g16 >> 3, gval = g16 & 7;
    int tile = lane >> 1, q = lane & 1;
    uint2 ev = __ldg((const uint2*)(g_eperm + (size_t)batch * 1024 +
                                   tile * 64 + sel * 32 + 4 * gval + 2 * q));
    float2 e01 = __half22float2(*(__half2*)&ev.x);
    float2 e23 = __half22float2(*(__half2*)&ev.y);

    float4 av = __ldg(&((const float4*)att)[lane]);

    float4 m = make_float4(lrelu(xl.x + xr.x + e01.x), lrelu(xl.y + xr.y + e01.y),
                           lrelu(xl.z + xr.z + e23.x), lrelu(xl.w + xr.w + e23.y));
    float p = m.x * av.x + m.y * av.y + m.z * av.z + m.w * av.w;
    p += __shfl_xor_sync(0xffffffffu, p, 4);
    p += __shfl_xor_sync(0xffffffffu, p, 2);
    p += __shfl_xor_sync(0xffffffffu, p, 1);

    float ex = __expf(p);

    if ((lane & 7) == 0)
        atomicAdd(&g_denom[(size_t)t * HH + (lane >> 3)], ex);

    red_add_v4(&g_accum[(long)t * 32 + lane],
               make_float4(ex * xl.x, ex * xl.y, ex * xl.z, ex * xl.w));
}

// ---------------- kernel 6: finalize (head mean + bias + LeakyReLU) --------
__global__ void finalize_kernel(const float* __restrict__ bias,
                                float* __restrict__ out) {
    int idx = blockIdx.x * blockDim.x + threadIdx.x;
    if (idx >= NN * OUTC) return;
    int n = idx >> 5, c = idx & 31;
    const float* acc = (const float*)g_accum;
    float sum = 0.f;
#pragma unroll
    for (int hh = 0; hh < HH; hh++)
        sum += acc[(size_t)n * HO + hh * OUTC + c] / g_denom[(size_t)n * HH + hh];
    float o = sum * 0.25f + bias[c];
    out[idx] = lrelu(o);
}

// ---------------- launch ---------------------------------------------------
extern "C" void kernel_launch(void* const* d_in, const int* in_sizes, int n_in,
                              void* d_out, int out_size) {
    const float* x     = (const float*)d_in[0];
    const int*   ei    = (const int*)  d_in[1];
    const float* eattr = (const float*)d_in[2];
    const float* Wl    = (const float*)d_in[3];
    const float* bl    = (const float*)d_in[4];
    const float* Wr    = (const float*)d_in[5];
    const float* br    = (const float*)d_in[6];
    const float* We    = (const float*)d_in[7];
    const float* att   = (const float*)d_in[8];
    const float* bias  = (const float*)d_in[9];
    float* out = (float*)d_out;

    zero_kernel<<<2048, 256>>>();
    deg_attr_kernel<<<(EE + 255) / 256, 256>>>(ei, eattr);
    gemm_xlr<<<(NN + 63) / 64, 256>>>(x, Wl, bl, Wr, br);
    egemm_mma_kernel<<<(NBATCH + 7) / 8, 256>>>(eattr, We);  // 8 warps/block
    edge_light_kernel<<<(ENF + 7) / 8, 256>>>(ei, att);
    finalize_kernel<<<(NN * OUTC + 255) / 256, 256>>>(bias, out);
}